// round 17
// baseline (speedup 1.0000x reference)
#include <cuda_runtime.h>
#include <cuda_fp16.h>
#include <cstdint>

// Problem constants (K_Rectify): B=128, NTOT=129, N=128, GS=16, C=384
#define PB    128
#define PNTOT 129
#define PN    128
#define PGS   16
#define PC    384
#define EPSW  0.05f
#define RMSE  1e-6f

#define NPTS (PB * PN)        // 16384
#define ROWB (PC * 2)         // staged row bytes = 768

// fp16 staging of the gatherable point rows f[:,1:,:], row j = idx value.
__device__ __align__(16) __half2 g_half[(size_t)NPTS * (PC / 2)];

static __device__ __forceinline__ __half2 u2h2(unsigned u) {
    __half2 h; *reinterpret_cast<unsigned*>(&h) = u; return h;
}
static __device__ __forceinline__ unsigned h22u(__half2 h) {
    return *reinterpret_cast<unsigned*>(&h);
}

// ---------------- Kernel 1: fp32 -> fp16 staging ----------------
__global__ void __launch_bounds__(256)
k_convert_kernel(const float* __restrict__ f)
{
    const int t  = blockIdx.x * blockDim.x + threadIdx.x;   // float4 slot
    const int r  = t / (PC / 4);                            // point row 0..16383
    const int c4 = t - r * (PC / 4);                        // float4 column 0..95

    const float4 v = reinterpret_cast<const float4*>(
        f + (size_t)((r >> 7) * PNTOT + 1 + (r & (PN - 1))) * PC)[c4];

    uint2 u;
    u.x = h22u(__floats2half2_rn(v.x, v.y));
    u.y = h22u(__floats2half2_rn(v.z, v.w));
    reinterpret_cast<uint2*>(g_half + (size_t)r * (PC / 2))[c4] = u;
}

// ---------------- Kernel 2: rectify ----------------
// 96 threads per CTA, one point per CTA; thread t owns channels [4t, 4t+4).
// All 16 neighbor rows staged into smem via cp.async (8 x 16B per thread,
// zero register pressure), then HFMA2 accumulation from smem.
__global__ void __launch_bounds__(96, 16)
k_rectify_kernel(const float* __restrict__ f,
                 const float* __restrict__ dist,
                 const float* __restrict__ rf,
                 const float* __restrict__ knw,
                 const int* __restrict__ idx,
                 float* __restrict__ out)
{
    const int p   = blockIdx.x;
    const int tid = threadIdx.x;

    if (p >= NPTS) {
        const int b = p - NPTS;
        const float4* src = reinterpret_cast<const float4*>(f  + (size_t)b * PNTOT * PC);
        float4*       dst = reinterpret_cast<float4*>(out + (size_t)b * PNTOT * PC);
        dst[tid] = src[tid];
        return;
    }

    const int b = p >> 7;
    const int n = p & (PN - 1);

    __shared__ __align__(16) char srows[PGS * ROWB];   // 16 x 768B neighbor rows
    __shared__ unsigned swh[PGS];                      // half2-packed weights
    __shared__ int      soff[PGS];                     // gather row byte offsets
    __shared__ float    sred[3];                       // per-warp RMS partials

    if (tid < PGS) {
        const float d = dist[p * PGS + tid];
        float wv = 1.0f / (d + EPSW);
        float s  = wv;
        #pragma unroll
        for (int o = 8; o > 0; o >>= 1)
            s += __shfl_xor_sync(0x0000FFFFu, s, o, 16);
        swh[tid]  = h22u(__float2half2_rn(wv / s));
        soff[tid] = idx[p * PGS + tid] * ROWB;         // row stride 768 bytes
    }
    __syncthreads();

    // Stage all 16 rows into smem: 768 chunks of 16B, 8 per thread.
    // Thread layout: h = tid/48 selects row parity, j = chunk within row.
    {
        const int h = tid / 48;           // 0 or 1
        const int j = tid - h * 48;       // 0..47
        const char* gb = reinterpret_cast<const char*>(g_half) + j * 16;
        const unsigned sb = (unsigned)__cvta_generic_to_shared(srows) + j * 16;
        #pragma unroll
        for (int i = 0; i < 8; i++) {
            const int row = 2 * i + h;
            asm volatile("cp.async.cg.shared.global [%0], [%1], 16;\n"
                         :: "r"(sb + row * ROWB), "l"(gb + soff[row]));
        }
        asm volatile("cp.async.commit_group;\n" ::: "memory");
    }

    // x row (fp32, exact) — independent LDG, overlaps the cp.async fill.
    const int xoff = (b * PNTOT + 1 + n) * PC;
    const float4 x4 = reinterpret_cast<const float4*>(f + (size_t)xoff)[tid];

    asm volatile("cp.async.wait_group 0;\n" ::: "memory");
    __syncthreads();

    // HFMA2 accumulation from smem, two banks (even/odd g) — same numerics as R15.
    const char* sb = srows + tid * 8;
    __half2 A0 = u2h2(0), A1 = u2h2(0);
    __half2 B0 = u2h2(0), B1 = u2h2(0);
    #pragma unroll
    for (int g = 0; g < PGS; g += 2) {
        const uint2 v0 = *reinterpret_cast<const uint2*>(sb + g * ROWB);
        const __half2 w0 = u2h2(swh[g]);
        A0 = __hfma2(w0, u2h2(v0.x), A0);
        A1 = __hfma2(w0, u2h2(v0.y), A1);
        const uint2 v1 = *reinterpret_cast<const uint2*>(sb + (g + 1) * ROWB);
        const __half2 w1 = u2h2(swh[g + 1]);
        B0 = __hfma2(w1, u2h2(v1.x), B0);
        B1 = __hfma2(w1, u2h2(v1.y), B1);
    }

    // Combine banks in fp32; sf = sum(w*nb) - x  (weights sum to 1)
    const float2 a0 = __half22float2(A0), b0f = __half22float2(B0);
    const float2 a1 = __half22float2(A1), b1f = __half22float2(B1);

    const float s0 = a0.x + b0f.x - x4.x;
    const float s1 = a0.y + b0f.y - x4.y;
    const float s2 = a1.x + b1f.x - x4.z;
    const float s3 = a1.y + b1f.y - x4.w;

    // RMS over the 384-channel row
    float ss = s0 * s0 + s1 * s1 + s2 * s2 + s3 * s3;
    #pragma unroll
    for (int o = 16; o > 0; o >>= 1)
        ss += __shfl_xor_sync(0xFFFFFFFFu, ss, o);
    if ((tid & 31) == 0) sred[tid >> 5] = ss;
    __syncthreads();
    const float tot = sred[0] + sred[1] + sred[2];
    const float inv = rsqrtf(tot * (1.0f / PC) + RMSE);

    // out = rf[1+n] + x + (sf * inv) * knorm_w
    const float4 r4 = reinterpret_cast<const float4*>(rf + (size_t)(1 + n) * PC)[tid];
    const float4 k4 = reinterpret_cast<const float4*>(knw)[tid];

    float4 o4;
    o4.x = r4.x + x4.x + s0 * inv * k4.x;
    o4.y = r4.y + x4.y + s1 * inv * k4.y;
    o4.z = r4.z + x4.z + s2 * inv * k4.z;
    o4.w = r4.w + x4.w + s3 * inv * k4.w;
    reinterpret_cast<float4*>(out + (size_t)xoff)[tid] = o4;
}

extern "C" void kernel_launch(void* const* d_in, const int* in_sizes, int n_in,
                              void* d_out, int out_size)
{
    const float* f    = (const float*)d_in[0];
    const float* dist = (const float*)d_in[1];
    const float* rf   = (const float*)d_in[2];
    const float* knw  = (const float*)d_in[3];
    const int*   idx  = (const int*)d_in[4];
    float*       out  = (float*)d_out;

    const int conv_threads = NPTS * (PC / 4);              // 1,572,864
    k_convert_kernel<<<conv_threads / 256, 256>>>(f);

    const int grid = NPTS + PB;                            // 16384 compute + 128 cls
    k_rectify_kernel<<<grid, 96>>>(f, dist, rf, knw, idx, out);
}